// round 1
// baseline (speedup 1.0000x reference)
#include <cuda_runtime.h>
#include <cuda_bf16.h>

#define BS_      1024
#define D_       1024
#define NEG_     32
#define V_       (D_ / 4)          // 256 float4 per row
#define THREADS_ 256
#define NVALS_   (3 + 2 * NEG_)    // 67 partials per thread
#define TEMPERATURE_ 0.05f
#define CLS_W_       0.2f
#define EPS_         1e-8f

__device__ float g_row_loss[BS_];

static __device__ __forceinline__ float warp_sum(float v) {
    #pragma unroll
    for (int o = 16; o > 0; o >>= 1)
        v += __shfl_xor_sync(0xffffffffu, v, o);
    return v;
}

static __device__ __forceinline__ float dot4(float4 a, float4 b) {
    return a.x * b.x + a.y * b.y + a.z * b.z + a.w * b.w;
}

__global__ __launch_bounds__(THREADS_, 2)
void cls_row_kernel(const float4* __restrict__ q,
                    const float4* __restrict__ p,
                    const float4* __restrict__ neg) {
    const int b    = blockIdx.x;
    const int t    = threadIdx.x;
    const int lane = t & 31;
    const int w    = t >> 5;

    // q slice in registers
    float4 qv = q[b * V_ + t];
    float4 pv = p[b * V_ + t];

    float vals[NVALS_];
    vals[0] = dot4(qv, qv);   // q·q
    vals[1] = dot4(pv, pv);   // p·p
    vals[2] = dot4(qv, pv);   // q·p

    const float4* nbase = neg + (size_t)b * NEG_ * V_;
    #pragma unroll 4
    for (int n = 0; n < NEG_; n++) {
        float4 nv = nbase[n * V_ + t];
        vals[3 + n]        = dot4(qv, nv);   // q·neg_n
        vals[3 + NEG_ + n] = dot4(nv, nv);   // neg_n·neg_n
    }

    // warp-level reduce all 67 partials
    #pragma unroll
    for (int i = 0; i < NVALS_; i++)
        vals[i] = warp_sum(vals[i]);

    __shared__ float red[8][NVALS_ + 1];  // +1 pad vs bank conflicts
    if (lane == 0) {
        #pragma unroll
        for (int i = 0; i < NVALS_; i++)
            red[w][i] = vals[i];
    }
    __syncthreads();

    __shared__ float fin[NVALS_];
    if (t < NVALS_) {
        float s = 0.f;
        #pragma unroll
        for (int ww = 0; ww < 8; ww++)
            s += red[ww][t];
        fin[t] = s;
    }
    __syncthreads();

    if (t == 0) {
        const float inv_T = 1.0f / TEMPERATURE_;
        float qq = fin[0], pp = fin[1], qp = fin[2];
        float qn  = fmaxf(sqrtf(qq), EPS_);
        float pn  = fmaxf(sqrtf(pp), EPS_);
        float sim0 = qp / (qn * pn) * inv_T;

        float sims[NEG_];
        float m = sim0;
        #pragma unroll
        for (int n = 0; n < NEG_; n++) {
            float nn = fmaxf(sqrtf(fin[3 + NEG_ + n]), EPS_);
            float s  = fin[3 + n] / (qn * nn) * inv_T;
            sims[n] = s;
            m = fmaxf(m, s);
        }
        float se = __expf(sim0 - m);
        #pragma unroll
        for (int n = 0; n < NEG_; n++)
            se += __expf(sims[n] - m);
        float lse = m + __logf(se);
        g_row_loss[b] = lse - sim0;   // = -log_softmax[:,0]
    }
}

__global__ void cls_reduce_kernel(float* __restrict__ out) {
    const int t    = threadIdx.x;
    const int lane = t & 31;
    const int w    = t >> 5;
    float v = g_row_loss[t];
    v = warp_sum(v);
    __shared__ float s[32];
    if (lane == 0) s[w] = v;
    __syncthreads();
    if (w == 0) {
        float x = s[lane];
        x = warp_sum(x);
        if (lane == 0)
            out[0] = x * (CLS_W_ / (float)BS_);
    }
}

extern "C" void kernel_launch(void* const* d_in, const int* in_sizes, int n_in,
                              void* d_out, int out_size) {
    const float4* q   = (const float4*)d_in[0];  // text_embeddings   [1024,1024]
    const float4* p   = (const float4*)d_in[1];  // text_pos_embeddings
    const float4* neg = (const float4*)d_in[2];  // text_neg_embeddings [32768,1024]
    float* out = (float*)d_out;

    cls_row_kernel<<<BS_, THREADS_>>>(q, p, neg);
    cls_reduce_kernel<<<1, BS_>>>(out);
}

// round 3
// speedup vs baseline: 2.2002x; 2.2002x over previous
#include <cuda_runtime.h>
#include <cuda_bf16.h>

#define BS_      1024
#define D_       1024
#define NEG_     32
#define V_       (D_ / 4)          // 256 float4 per row
#define TEMPERATURE_ 0.05f
#define CLS_W_       0.2f
#define EPS_         1e-8f

__device__ float g_row_loss[BS_];

static __device__ __forceinline__ float warp_sum(float v) {
    #pragma unroll
    for (int o = 16; o > 0; o >>= 1)
        v += __shfl_xor_sync(0xffffffffu, v, o);
    return v;
}

static __device__ __forceinline__ float dot4(float4 a, float4 b) {
    return a.x * b.x + a.y * b.y + a.z * b.z + a.w * b.w;
}

__global__ __launch_bounds__(256)
void cls_row_kernel(const float4* __restrict__ q,
                    const float4* __restrict__ p,
                    const float4* __restrict__ neg) {
    const int b    = blockIdx.x;
    const int t    = threadIdx.x;
    const int lane = t & 31;
    const int w    = t >> 5;

    // Each lane keeps its 8-float4 slice of the q row in registers.
    // Element map: lane l covers float4 indices {j*32 + l}, j=0..7 (coalesced).
    const float4* rq = q + b * V_;
    float4 qv[8];
    #pragma unroll
    for (int j = 0; j < 8; j++)
        qv[j] = rq[j * 32 + lane];

    __shared__ float s_qn[NEG_];
    __shared__ float s_nn[NEG_];
    __shared__ float s3[3];   // qq, pp, qp

    // Warp w owns negatives 4w .. 4w+3. Accumulate per-k partials in
    // registers; defer ALL warp reductions past the load loop so the
    // SHFL chains never sit between load batches (max MLP).
    const float4* nb = neg + (size_t)b * NEG_ * V_;
    float accq[4], accn[4];
    #pragma unroll
    for (int k = 0; k < 4; k++) {
        const float4* rn = nb + (4 * w + k) * V_;
        float4 nv[8];
        #pragma unroll
        for (int j = 0; j < 8; j++)
            nv[j] = rn[j * 32 + lane];
        float qn = 0.f, nn = 0.f;
        #pragma unroll
        for (int j = 0; j < 8; j++) {
            qn += dot4(qv[j], nv[j]);
            nn += dot4(nv[j], nv[j]);
        }
        accq[k] = qn;
        accn[k] = nn;
    }
    #pragma unroll
    for (int k = 0; k < 4; k++) {
        float qn = warp_sum(accq[k]);
        float nn = warp_sum(accn[k]);
        if (lane == 0) {
            s_qn[4 * w + k] = qn;
            s_nn[4 * w + k] = nn;
        }
    }

    // Warp 0 additionally handles q·q, p·p, q·p.
    if (w == 0) {
        const float4* rp = p + b * V_;
        float qq = 0.f, pp = 0.f, qp = 0.f;
        #pragma unroll
        for (int j = 0; j < 8; j++) {
            float4 pv = rp[j * 32 + lane];
            qq += dot4(qv[j], qv[j]);
            pp += dot4(pv, pv);
            qp += dot4(qv[j], pv);
        }
        qq = warp_sum(qq);
        pp = warp_sum(pp);
        qp = warp_sum(qp);
        if (lane == 0) { s3[0] = qq; s3[1] = pp; s3[2] = qp; }
    }
    __syncthreads();

    if (t == 0) {
        const float inv_T = 1.0f / TEMPERATURE_;
        float qn  = fmaxf(sqrtf(s3[0]), EPS_);
        float pn  = fmaxf(sqrtf(s3[1]), EPS_);
        float sim0 = s3[2] / (qn * pn) * inv_T;

        float sims[NEG_];
        float m = sim0;
        #pragma unroll
        for (int n = 0; n < NEG_; n++) {
            float nn = fmaxf(sqrtf(s_nn[n]), EPS_);
            float s  = s_qn[n] / (qn * nn) * inv_T;
            sims[n] = s;
            m = fmaxf(m, s);
        }
        float se = __expf(sim0 - m);
        #pragma unroll
        for (int n = 0; n < NEG_; n++)
            se += __expf(sims[n] - m);
        float lse = m + __logf(se);
        g_row_loss[b] = lse - sim0;   // = -log_softmax[:, 0]
    }
}

__global__ void cls_reduce_kernel(float* __restrict__ out) {
    const int t    = threadIdx.x;
    const int lane = t & 31;
    const int w    = t >> 5;
    float v = g_row_loss[t];
    v = warp_sum(v);
    __shared__ float s[32];
    if (lane == 0) s[w] = v;
    __syncthreads();
    if (w == 0) {
        float x = s[lane];
        x = warp_sum(x);
        if (lane == 0)
            out[0] = x * (CLS_W_ / (float)BS_);
    }
}

extern "C" void kernel_launch(void* const* d_in, const int* in_sizes, int n_in,
                              void* d_out, int out_size) {
    const float4* q   = (const float4*)d_in[0];  // text_embeddings     [1024,1024]
    const float4* p   = (const float4*)d_in[1];  // text_pos_embeddings [1024,1024]
    const float4* neg = (const float4*)d_in[2];  // text_neg_embeddings [32768,1024]
    float* out = (float*)d_out;

    cls_row_kernel<<<BS_, 256>>>(q, p, neg);
    cls_reduce_kernel<<<1, BS_>>>(out);
}